// round 1
// baseline (speedup 1.0000x reference)
#include <cuda_runtime.h>

#define KS 13
#define RAD 6
#define TW 32
#define TH 8
#define PW (TW + 2*RAD)   // 44
#define PH (TH + 2*RAD)   // 20
#define IMH 256
#define IMW 256
#define NC 4
#define NB 2

__device__ __forceinline__ float fast_ex2(float x) {
    float r;
    asm("ex2.approx.ftz.f32 %0, %1;" : "=f"(r) : "f"(x));
    return r;
}
__device__ __forceinline__ float fast_lg2(float x) {
    float r;
    asm("lg2.approx.f32 %0, %1;" : "=f"(r) : "f"(x));
    return r;
}
__device__ __forceinline__ float fast_exp(float x) {
    // e^x = 2^(x*log2e)
    return fast_ex2(x * 1.4426950408889634f);
}

__global__ __launch_bounds__(256, 4)
void bilateral13_kernel(const float* __restrict__ x, float* __restrict__ out) {
    __shared__ float4 tile[PH][PW];
    __shared__ float s_ls[KS * KS];   // log2(space kernel)

    const int tid = threadIdx.x;          // 0..255
    const int b   = blockIdx.z;
    const int tx0 = blockIdx.x * TW;
    const int ty0 = blockIdx.y * TH;

    // ---- per-block: log2-domain separable spatial Gaussian -----------------
    if (tid < KS * KS) {
        const int iy = tid / KS, ix = tid % KS;
        float S = 0.f;
        #pragma unroll
        for (int i = 0; i < KS; i++) {
            float d = (float)(i - RAD) * (1.0f / 3.0f);
            S += fast_exp(-0.5f * d * d);
        }
        float dy = (float)(iy - RAD) * (1.0f / 3.0f);
        float dx = (float)(ix - RAD) * (1.0f / 3.0f);
        float gy = fast_exp(-0.5f * dy * dy);
        float gx = fast_exp(-0.5f * dx * dx);
        s_ls[tid] = fast_lg2((gy * gx) / (S * S));
    }

    // ---- cooperative load of reflect-padded tile, channels packed float4 --
    const float* xb = x + (size_t)b * NC * IMH * IMW;
    for (int i = tid; i < PH * PW; i += 256) {
        int py = i / PW, px = i % PW;
        int gy = ty0 + py - RAD;
        int gx = tx0 + px - RAD;
        gy = (gy < 0) ? -gy : ((gy >= IMH) ? (2 * IMH - 2 - gy) : gy);
        gx = (gx < 0) ? -gx : ((gx >= IMW) ? (2 * IMW - 2 - gx) : gx);
        int g = gy * IMW + gx;
        float4 v;
        v.x = xb[0 * IMH * IMW + g];
        v.y = xb[1 * IMH * IMW + g];
        v.z = xb[2 * IMH * IMW + g];
        v.w = xb[3 * IMH * IMW + g];
        tile[py][px] = v;
    }
    __syncthreads();

    // ---- per-thread: one output pixel --------------------------------------
    const int lx = tid & (TW - 1);  // 0..31
    const int ly = tid >> 5;        // 0..7

    const float4 c = tile[ly + RAD][lx + RAD];

    // exponent scale: -0.5/sigma_color^2 * log2(e)
    const float K2 = (-0.5f / 9.0f) * 1.4426950408889634f;

    float acc0 = 0.f, acc1 = 0.f, acc2 = 0.f, acc3 = 0.f, wsum = 0.f;

    #pragma unroll 1
    for (int iy = 0; iy < KS; iy++) {
        const float4* row   = &tile[ly + iy][lx];
        const float*  lsrow = &s_ls[iy * KS];
        #pragma unroll
        for (int ix = 0; ix < KS; ix++) {
            float4 p = row[ix];
            float d = fabsf(p.x - c.x) + fabsf(p.y - c.y)
                    + fabsf(p.z - c.z) + fabsf(p.w - c.w);
            float w = fast_ex2(fmaf(d * d, K2, lsrow[ix]));
            wsum += w;
            acc0 = fmaf(w, p.x, acc0);
            acc1 = fmaf(w, p.y, acc1);
            acc2 = fmaf(w, p.z, acc2);
            acc3 = fmaf(w, p.w, acc3);
        }
    }

    const float inv = __fdividef(1.0f, wsum);
    float* ob = out + (size_t)b * NC * IMH * IMW;
    const int o = (ty0 + ly) * IMW + (tx0 + lx);
    ob[0 * IMH * IMW + o] = acc0 * inv;
    ob[1 * IMH * IMW + o] = acc1 * inv;
    ob[2 * IMH * IMW + o] = acc2 * inv;
    ob[3 * IMH * IMW + o] = acc3 * inv;
}

extern "C" void kernel_launch(void* const* d_in, const int* in_sizes, int n_in,
                              void* d_out, int out_size) {
    const float* x = (const float*)d_in[0];
    float* out = (float*)d_out;
    dim3 grid(IMW / TW, IMH / TH, NB);   // 8 x 32 x 2 = 512 blocks
    bilateral13_kernel<<<grid, 256>>>(x, out);
}